// round 4
// baseline (speedup 1.0000x reference)
#include <cuda_runtime.h>
#include <math_constants.h>

// ---------------------------------------------------------------------------
// CasualAttention via packed fp32x2 FMA (Blackwell FFMA2) + double buffering.
// B=4, S=2048, D=1024, fp32. Same 4-launch pipeline as R2:
//   1) qkv_kernel    : C[8192,3072] = X @ [Wq|Wk|Wv]
//   2) scores_kernel : per-batch Q K^T * scale, lower-triangular tiles only
//   3) softmax_kernel: causal row softmax (zeros above diagonal)
//   4) av_kernel     : P @ V, K-loop truncated at causal bound
// Inner loops use fma.rn.f32x2 (2 fp32 FMA / instr) with the A operand stored
// duplicated in smem so the broadcast pair {a,a} is a plain 64-bit LDS.
// ---------------------------------------------------------------------------

#define BM 128
#define BN 128
#define BK 16
#define TM 8
#define TN 8

static constexpr int Bb = 4;
static constexpr int S  = 2048;
static constexpr int D  = 1024;
static constexpr int M1 = Bb * S;   // 8192
static constexpr int N1 = 3 * D;    // 3072

// Scratch (__device__ globals: allocation-free rule)
__device__ float g_q[M1 * D];
__device__ float g_k[M1 * D];
__device__ float g_v[M1 * D];
__device__ float g_p[(size_t)Bb * S * S];

typedef unsigned long long u64;

__device__ __forceinline__ void ffma2(u64& d, u64 a, u64 b) {
    // d.lo = a.lo*b.lo + d.lo ; d.hi = a.hi*b.hi + d.hi   (SASS FFMA2)
    asm("fma.rn.f32x2 %0, %1, %2, %0;" : "+l"(d) : "l"(a), "l"(b));
}
__device__ __forceinline__ float f_lo(u64 v) { return __uint_as_float((unsigned)v); }
__device__ __forceinline__ float f_hi(u64 v) { return __uint_as_float((unsigned)(v >> 32)); }

// ---------------------------------------------------------------------------
// Shared-memory tile loaders (register-staged for double buffering)
// ---------------------------------------------------------------------------

// A-side: 128 rows x 16 k, loaded as float4 along k, scattered transposed and
// DUPLICATED into As[kk][2m]=As[kk][2m+1]=A[m][kk].
__device__ __forceinline__ void load_a_regs(const float* __restrict__ src, int ld,
                                            int row0, int k0, int t, float4 (&r)[2]) {
    #pragma unroll
    for (int it = 0; it < 2; it++) {
        int idx = t + it * 256;            // 0..511
        int m   = idx >> 2;                // 0..127
        int kq  = (idx & 3) * 4;           // 0,4,8,12
        r[it] = *(const float4*)(src + (size_t)(row0 + m) * ld + k0 + kq);
    }
}
__device__ __forceinline__ void store_a_dup(float (&As)[BK][2 * BM], int t,
                                            const float4 (&r)[2]) {
    #pragma unroll
    for (int it = 0; it < 2; it++) {
        int idx = t + it * 256;
        int m   = idx >> 2;
        int kq  = (idx & 3) * 4;
        *(float2*)&As[kq + 0][2 * m] = make_float2(r[it].x, r[it].x);
        *(float2*)&As[kq + 1][2 * m] = make_float2(r[it].y, r[it].y);
        *(float2*)&As[kq + 2][2 * m] = make_float2(r[it].z, r[it].z);
        *(float2*)&As[kq + 3][2 * m] = make_float2(r[it].w, r[it].w);
    }
}

// B-side, row-major source (W for qkv, V for av): Bs[row][c] = B[k0+row][col0+c]
__device__ __forceinline__ void load_b_rows(const float* __restrict__ src, int ld,
                                            int k0, int col0, int t, float4 (&r)[2]) {
    #pragma unroll
    for (int it = 0; it < 2; it++) {
        int idx = t + it * 256;
        int row = idx >> 5;                // 0..15
        int c   = (idx & 31) * 4;          // 0..124
        r[it] = *(const float4*)(src + (size_t)(k0 + row) * ld + col0 + c);
    }
}
__device__ __forceinline__ void store_b_rows(float (&Bs)[BK][BN], int t,
                                             const float4 (&r)[2]) {
    #pragma unroll
    for (int it = 0; it < 2; it++) {
        int idx = t + it * 256;
        int row = idx >> 5;
        int c   = (idx & 31) * 4;
        *(float4*)&Bs[row][c] = r[it];
    }
}

// B-side, k-contiguous source (K matrix for scores): transposed scatter.
__device__ __forceinline__ void store_b_trans(float (&Bs)[BK][BN], int t,
                                              const float4 (&r)[2]) {
    #pragma unroll
    for (int it = 0; it < 2; it++) {
        int idx = t + it * 256;
        int n   = idx >> 2;                // 0..127
        int kq  = (idx & 3) * 4;
        Bs[kq + 0][n] = r[it].x;
        Bs[kq + 1][n] = r[it].y;
        Bs[kq + 2][n] = r[it].z;
        Bs[kq + 3][n] = r[it].w;
    }
}

// ---------------------------------------------------------------------------
// FFMA2 tile compute: 8x8 per thread as 8x4 fp32x2 pairs.
// ---------------------------------------------------------------------------
__device__ __forceinline__ void mma_tile(const float (&As)[BK][2 * BM],
                                         const float (&Bs)[BK][BN],
                                         int tx, int ty, u64 (&acc)[TM][TN / 2]) {
    #pragma unroll
    for (int kk = 0; kk < BK; kk++) {
        const ulonglong2* ap = (const ulonglong2*)&As[kk][2 * (ty * TM)];
        ulonglong2 av0 = ap[0], av1 = ap[1], av2 = ap[2], av3 = ap[3];
        const ulonglong2* bp = (const ulonglong2*)&Bs[kk][tx * TN];
        ulonglong2 bv0 = bp[0], bv1 = bp[1];
        u64 a2[TM] = {av0.x, av0.y, av1.x, av1.y, av2.x, av2.y, av3.x, av3.y};
        u64 b2[TN / 2] = {bv0.x, bv0.y, bv1.x, bv1.y};
        #pragma unroll
        for (int i = 0; i < TM; i++)
            #pragma unroll
            for (int j = 0; j < TN / 2; j++)
                ffma2(acc[i][j], a2[i], b2[j]);
    }
}

// ---------------------------------------------------------------------------
// Kernel 1: fused QKV projection
// ---------------------------------------------------------------------------
__global__ __launch_bounds__(256, 2) void qkv_kernel(
    const float* __restrict__ X,
    const float* __restrict__ Wq,
    const float* __restrict__ Wk,
    const float* __restrict__ Wv)
{
    __shared__ float As[2][BK][2 * BM];   // 32 KB (duplicated A)
    __shared__ float Bs[2][BK][BN];       // 16 KB

    const int n0 = blockIdx.x * BN;
    const int m0 = blockIdx.y * BM;
    const int which = n0 >> 10;
    const float* __restrict__ W = (which == 0) ? Wq : ((which == 1) ? Wk : Wv);
    float* __restrict__ Out     = (which == 0) ? g_q : ((which == 1) ? g_k : g_v);
    const int nW = n0 & (D - 1);

    const int t  = threadIdx.x;
    const int tx = t & 15;
    const int ty = t >> 4;

    u64 acc[TM][TN / 2];
    #pragma unroll
    for (int i = 0; i < TM; i++)
        #pragma unroll
        for (int j = 0; j < TN / 2; j++) acc[i][j] = 0ULL;

    float4 ra[2], rb[2];
    load_a_regs(X, D, m0, 0, t, ra);
    load_b_rows(W, D, 0, nW, t, rb);
    store_a_dup(As[0], t, ra);
    store_b_rows(Bs[0], t, rb);
    __syncthreads();

    int cur = 0;
    for (int k0 = 0; k0 < D; k0 += BK) {
        const bool has_next = (k0 + BK) < D;
        if (has_next) {
            load_a_regs(X, D, m0, k0 + BK, t, ra);
            load_b_rows(W, D, k0 + BK, nW, t, rb);
        }
        mma_tile(As[cur], Bs[cur], tx, ty, acc);
        if (has_next) {
            store_a_dup(As[cur ^ 1], t, ra);
            store_b_rows(Bs[cur ^ 1], t, rb);
        }
        __syncthreads();
        cur ^= 1;
    }

    #pragma unroll
    for (int i = 0; i < TM; i++) {
        const int gm = m0 + ty * TM + i;
        float4 v0 = make_float4(f_lo(acc[i][0]), f_hi(acc[i][0]),
                                f_lo(acc[i][1]), f_hi(acc[i][1]));
        float4 v1 = make_float4(f_lo(acc[i][2]), f_hi(acc[i][2]),
                                f_lo(acc[i][3]), f_hi(acc[i][3]));
        *(float4*)(Out + (size_t)gm * D + nW + tx * TN + 0) = v0;
        *(float4*)(Out + (size_t)gm * D + nW + tx * TN + 4) = v1;
    }
}

// ---------------------------------------------------------------------------
// Kernel 2: scores = Q K^T * scale (lower-triangular tiles only)
// ---------------------------------------------------------------------------
__global__ __launch_bounds__(256, 2) void scores_kernel()
{
    const int jt = blockIdx.x;
    const int it = blockIdx.y;
    if (jt > it) return;
    const int b  = blockIdx.z;

    const int i0 = it * BM;
    const int j0 = jt * BN;
    const float* __restrict__ Q  = g_q + (size_t)b * S * D;
    const float* __restrict__ Km = g_k + (size_t)b * S * D;
    float* __restrict__ P        = g_p + (size_t)b * S * S;

    __shared__ float As[2][BK][2 * BM];
    __shared__ float Bs[2][BK][BN];

    const int t  = threadIdx.x;
    const int tx = t & 15;
    const int ty = t >> 4;

    u64 acc[TM][TN / 2];
    #pragma unroll
    for (int i = 0; i < TM; i++)
        #pragma unroll
        for (int j = 0; j < TN / 2; j++) acc[i][j] = 0ULL;

    float4 ra[2], rb[2];
    load_a_regs(Q, D, i0, 0, t, ra);
    load_a_regs(Km, D, j0, 0, t, rb);     // K rows are k-contiguous: A-style load
    store_a_dup(As[0], t, ra);
    store_b_trans(Bs[0], t, rb);
    __syncthreads();

    int cur = 0;
    for (int k0 = 0; k0 < D; k0 += BK) {
        const bool has_next = (k0 + BK) < D;
        if (has_next) {
            load_a_regs(Q, D, i0, k0 + BK, t, ra);
            load_a_regs(Km, D, j0, k0 + BK, t, rb);
        }
        mma_tile(As[cur], Bs[cur], tx, ty, acc);
        if (has_next) {
            store_a_dup(As[cur ^ 1], t, ra);
            store_b_trans(Bs[cur ^ 1], t, rb);
        }
        __syncthreads();
        cur ^= 1;
    }

    const float scale = 0.03125f;         // 1/sqrt(1024)
    if (jt < it) {
        #pragma unroll
        for (int i = 0; i < TM; i++) {
            const int gi = i0 + ty * TM + i;
            float4 v0 = make_float4(f_lo(acc[i][0]) * scale, f_hi(acc[i][0]) * scale,
                                    f_lo(acc[i][1]) * scale, f_hi(acc[i][1]) * scale);
            float4 v1 = make_float4(f_lo(acc[i][2]) * scale, f_hi(acc[i][2]) * scale,
                                    f_lo(acc[i][3]) * scale, f_hi(acc[i][3]) * scale);
            *(float4*)(P + (size_t)gi * S + j0 + tx * TN + 0) = v0;
            *(float4*)(P + (size_t)gi * S + j0 + tx * TN + 4) = v1;
        }
    } else {
        #pragma unroll
        for (int i = 0; i < TM; i++) {
            const int gi = i0 + ty * TM + i;
            float vals[TN] = {f_lo(acc[i][0]), f_hi(acc[i][0]), f_lo(acc[i][1]), f_hi(acc[i][1]),
                              f_lo(acc[i][2]), f_hi(acc[i][2]), f_lo(acc[i][3]), f_hi(acc[i][3])};
            #pragma unroll
            for (int j = 0; j < TN; j++) {
                const int gj = j0 + tx * TN + j;
                if (gj <= gi) P[(size_t)gi * S + gj] = vals[j] * scale;
            }
        }
    }
}

// ---------------------------------------------------------------------------
// Kernel 3: causal row softmax (zeros above diagonal)
// ---------------------------------------------------------------------------
__global__ __launch_bounds__(256) void softmax_kernel()
{
    const int r = blockIdx.x;
    const int i = r & (S - 1);
    float* __restrict__ row = g_p + (size_t)r * S;
    const int t = threadIdx.x;

    float v[8];
    float mx = -CUDART_INF_F;
    #pragma unroll
    for (int k = 0; k < 8; k++) {
        const int j = t + k * 256;
        v[k] = (j <= i) ? row[j] : -CUDART_INF_F;
        mx = fmaxf(mx, v[k]);
    }

    __shared__ float red[256];
    red[t] = mx;
    __syncthreads();
    #pragma unroll
    for (int s = 128; s > 0; s >>= 1) {
        if (t < s) red[t] = fmaxf(red[t], red[t + s]);
        __syncthreads();
    }
    mx = red[0];
    __syncthreads();

    float sum = 0.f;
    #pragma unroll
    for (int k = 0; k < 8; k++) {
        v[k] = __expf(v[k] - mx);
        sum += v[k];
    }
    red[t] = sum;
    __syncthreads();
    #pragma unroll
    for (int s = 128; s > 0; s >>= 1) {
        if (t < s) red[t] += red[t + s];
        __syncthreads();
    }
    const float inv = 1.0f / red[0];

    #pragma unroll
    for (int k = 0; k < 8; k++) {
        const int j = t + k * 256;
        row[j] = v[k] * inv;
    }
}

// ---------------------------------------------------------------------------
// Kernel 4: out = P @ V (causally truncated K-loop)
// ---------------------------------------------------------------------------
__global__ __launch_bounds__(256, 2) void av_kernel(float* __restrict__ OutAll)
{
    const int nt = blockIdx.x;
    const int mt = blockIdx.y;
    const int b  = blockIdx.z;
    const int m0 = mt * BM;
    const int n0 = nt * BN;

    const float* __restrict__ P = g_p + (size_t)b * S * S;
    const float* __restrict__ V = g_v + (size_t)b * S * D;
    float* __restrict__ O       = OutAll + (size_t)b * S * D;

    __shared__ float As[2][BK][2 * BM];
    __shared__ float Bs[2][BK][BN];

    const int t  = threadIdx.x;
    const int tx = t & 15;
    const int ty = t >> 4;

    u64 acc[TM][TN / 2];
    #pragma unroll
    for (int i = 0; i < TM; i++)
        #pragma unroll
        for (int j = 0; j < TN / 2; j++) acc[i][j] = 0ULL;

    const int kmax = m0 + BM;             // probs zero beyond the diagonal

    float4 ra[2], rb[2];
    load_a_regs(P, S, m0, 0, t, ra);
    load_b_rows(V, D, 0, n0, t, rb);
    store_a_dup(As[0], t, ra);
    store_b_rows(Bs[0], t, rb);
    __syncthreads();

    int cur = 0;
    for (int k0 = 0; k0 < kmax; k0 += BK) {
        const bool has_next = (k0 + BK) < kmax;
        if (has_next) {
            load_a_regs(P, S, m0, k0 + BK, t, ra);
            load_b_rows(V, D, k0 + BK, n0, t, rb);
        }
        mma_tile(As[cur], Bs[cur], tx, ty, acc);
        if (has_next) {
            store_a_dup(As[cur ^ 1], t, ra);
            store_b_rows(Bs[cur ^ 1], t, rb);
        }
        __syncthreads();
        cur ^= 1;
    }

    #pragma unroll
    for (int i = 0; i < TM; i++) {
        const int gm = m0 + ty * TM + i;
        float4 v0 = make_float4(f_lo(acc[i][0]), f_hi(acc[i][0]),
                                f_lo(acc[i][1]), f_hi(acc[i][1]));
        float4 v1 = make_float4(f_lo(acc[i][2]), f_hi(acc[i][2]),
                                f_lo(acc[i][3]), f_hi(acc[i][3]));
        *(float4*)(O + (size_t)gm * D + n0 + tx * TN + 0) = v0;
        *(float4*)(O + (size_t)gm * D + n0 + tx * TN + 4) = v1;
    }
}

// ---------------------------------------------------------------------------
extern "C" void kernel_launch(void* const* d_in, const int* in_sizes, int n_in,
                              void* d_out, int out_size)
{
    const float* x  = (const float*)d_in[0];
    const float* Wq = (const float*)d_in[1];
    const float* Wk = (const float*)d_in[2];
    const float* Wv = (const float*)d_in[3];
    float* out      = (float*)d_out;

    qkv_kernel<<<dim3(N1 / BN, M1 / BM), 256>>>(x, Wq, Wk, Wv);
    scores_kernel<<<dim3(S / BN, S / BM, Bb), 256>>>();
    softmax_kernel<<<Bb * S, 256>>>();
    av_kernel<<<dim3(D / BN, S / BM, Bb), 256>>>(out);
}